// round 5
// baseline (speedup 1.0000x reference)
#include <cuda_runtime.h>
#include <math.h>

#define NB_ALL 128
#define NB_S    64
#define NT     256
#define ROWS_B   8
#define ROWS_S  16
#define NN    1024
#define CC      64
#define NITERS  20
#define LSCALE 0.001f
#define NSLOT   48

// ---------------- device globals (no cudaMalloc allowed) ----------------
__device__ float g_psT[CC * NN];   // transposed softmax of y_s[7]  [C][N]
__device__ float g_ptT[CC * NN];   // transposed softmax of y_t[7]  [C][N]
__device__ float g_W[NN * NN];
__device__ float g_K[NN * NN];
__device__ float g_u[NN];
__device__ float g_v[NN];
__device__ float g_partial[NB_S];
// per-(slot,block) generation flags; zero-init; +1 per replay per written cell
__device__ __align__(512) unsigned g_fl[NSLOT * 128];

// ---------------- reductions ----------------
__device__ __forceinline__ float warp_sum(float v) {
#pragma unroll
    for (int o = 16; o > 0; o >>= 1) v += __shfl_down_sync(0xffffffffu, v, o);
    return v;
}
__device__ __forceinline__ float warp_max(float v) {
#pragma unroll
    for (int o = 16; o > 0; o >>= 1) v = fmaxf(v, __shfl_down_sync(0xffffffffu, v, o));
    return v;
}
__device__ float block_sum(float v, float* sc) {
    int t = threadIdx.x;
    v = warp_sum(v);
    if ((t & 31) == 0) sc[t >> 5] = v;
    __syncthreads();
    if (t == 0) {
        float r = 0.f;
#pragma unroll
        for (int i = 0; i < 8; i++) r += sc[i];
        sc[8] = r;
    }
    __syncthreads();
    float r = sc[8];
    __syncthreads();
    return r;
}
__device__ float block_max(float v, float* sc) {
    int t = threadIdx.x;
    v = warp_max(v);
    if ((t & 31) == 0) sc[t >> 5] = v;
    __syncthreads();
    if (t == 0) {
        float r = -3.4e38f;
#pragma unroll
        for (int i = 0; i < 8; i++) r = fmaxf(r, sc[i]);
        sc[8] = r;
    }
    __syncthreads();
    float r = sc[8];
    __syncthreads();
    return r;
}

// ---------------- atomic-free flag-array barrier ----------------
// post: block b publishes "slot done" (release orders all its prior stores).
__device__ __forceinline__ void post(int slot, int b, unsigned tag) {
    __syncthreads();
    if (threadIdx.x == 0) {
        unsigned* p = &g_fl[slot * 128 + b];
        asm volatile("st.release.gpu.global.u32 [%0], %1;"
                     :: "l"(p), "r"(tag) : "memory");
    }
}
// wait: warp 0 polls producer flags (pairs via b64 acquire loads), then the
// block syncs. Tags are monotonic; >= comparison is replay-safe.
__device__ __forceinline__ void wait_flags(int slot, int nprod, unsigned tag) {
    if (threadIdx.x < 32) {
        const unsigned* base = &g_fl[slot * 128];
        int npair = nprod >> 1;
        for (int q = threadIdx.x; q < npair; q += 32) {
            const unsigned* p = base + 2 * q;
            unsigned long long x;
            unsigned a, c;
            do {
                asm volatile("ld.acquire.gpu.global.b64 %0, [%1];"
                             : "=l"(x) : "l"(p) : "memory");
                a = (unsigned)x;
                c = (unsigned)(x >> 32);
            } while (a < tag || c < tag);
        }
    }
    __syncthreads();
}

// Sinkhorn half-step: rows 2w,2w+1 of Krows dotted with gin; gout = 1/dot.
__device__ __forceinline__ void halfstep(const float* __restrict__ Krows,
                                         const float* __restrict__ gin,
                                         float* __restrict__ gout,
                                         int i0, float* sVec, int t) {
    ((float4*)sVec)[t] = __ldcg(((const float4*)gin) + t);   // L2-coherent
    __syncthreads();
    int w = t >> 5, l = t & 31;
    const float* K0 = Krows + (2 * w) * NN;
    const float* K1 = K0 + NN;
    float s0 = 0.f, s1 = 0.f;
#pragma unroll
    for (int k = 0; k < 8; k++) {
        int j = (l + k * 32) * 4;
        float4 vv = *(const float4*)&sVec[j];
        float4 a  = *(const float4*)&K0[j];
        float4 c  = *(const float4*)&K1[j];
        s0 += a.x * vv.x + a.y * vv.y + a.z * vv.z + a.w * vv.w;
        s1 += c.x * vv.x + c.y * vv.y + c.z * vv.z + c.w * vv.w;
    }
    s0 = warp_sum(s0);
    s1 = warp_sum(s1);
    if (l == 0) {
        gout[i0 + 2 * w]     = 1.0f / s0;
        gout[i0 + 2 * w + 1] = 1.0f / s1;
    }
}

// ---------------- fused persistent kernel ----------------
__global__ __launch_bounds__(NT) void fused_kernel(const float* __restrict__ ys,
                                                   const float* __restrict__ yt,
                                                   float* __restrict__ out) {
    extern __shared__ float sm[];
    float* sK   = sm;                         // 16*1024
    float* sKT  = sm + ROWS_S * NN;           // 16*1024
    float* sVec = sm + 2 * ROWS_S * NN;       // 1024
    float* sPS  = sVec + NN;                  // 8*64
    float* sRed = sPS + ROWS_B * CC;          // 16

    __shared__ unsigned sTag;
    int b = blockIdx.x, t = threadIdx.x;
    if (t == 0) {
        unsigned r;
        asm volatile("ld.relaxed.gpu.global.u32 %0, [%1];"
                     : "=r"(r) : "l"(&g_fl[b]) : "memory");   // own slot-0 cell
        sTag = r + 1u;
    }
    __syncthreads();
    const unsigned tag = sTag;

    // ---- Phase A: softmax over N axis for batch sample 7 (one channel/block)
    {
        const float* y = (b < CC) ? ys : yt;
        float* pT      = (b < CC) ? g_psT : g_ptT;
        int c = b & (CC - 1);
        const float* base = y + 7 * NN * CC;
        float vals[4];
        float mx = -3.4e38f;
#pragma unroll
        for (int k = 0; k < 4; k++) {
            vals[k] = base[(t + k * NT) * CC + c] * 0.5f;   // y / T, T=2
            mx = fmaxf(mx, vals[k]);
        }
        mx = block_max(mx, sRed);
        float s = 0.f;
#pragma unroll
        for (int k = 0; k < 4; k++) { vals[k] = expf(vals[k] - mx); s += vals[k]; }
        s = block_sum(s, sRed);
        float inv = 1.0f / s;
#pragma unroll
        for (int k = 0; k < 4; k++) pT[c * NN + t + k * NT] = vals[k] * inv;
    }
    post(0, b, tag);
    wait_flags(0, NB_ALL, tag);

    // ---- Phase B: 8 W/K rows per block via packed f32x2 ----
    {
        int i0b = b * ROWS_B;
        for (int idx = t; idx < ROWS_B * CC; idx += NT) {
            int i = idx >> 6, c = idx & 63;
            sPS[idx] = g_psT[c * NN + i0b + i];
        }
        __syncthreads();

        const unsigned long long SMASK = 0x8000000080000000ULL;
        const unsigned long long AMASK = 0x7FFFFFFF7FFFFFFFULL;
        unsigned long long acc0[ROWS_B], acc1[ROWS_B];
#pragma unroll
        for (int i = 0; i < ROWS_B; i++) { acc0[i] = 0ULL; acc1[i] = 0ULL; }

        int j0 = t * 4;
        for (int c = 0; c < CC; c++) {
            ulonglong2 bv = *(const ulonglong2*)&g_ptT[c * NN + j0];
            unsigned long long nb0 = bv.x ^ SMASK;
            unsigned long long nb1 = bv.y ^ SMASK;
#pragma unroll
            for (int i = 0; i < ROWS_B; i++) {
                unsigned ai = __float_as_uint(sPS[i * CC + c]);
                unsigned long long aa, d0, d1;
                asm("mov.b64 %0, {%1, %1};" : "=l"(aa) : "r"(ai));
                asm("add.rn.f32x2 %0, %1, %2;" : "=l"(d0) : "l"(aa), "l"(nb0));
                asm("add.rn.f32x2 %0, %1, %2;" : "=l"(d1) : "l"(aa), "l"(nb1));
                d0 &= AMASK;
                d1 &= AMASK;
                asm("add.rn.f32x2 %0, %0, %1;" : "+l"(acc0[i]) : "l"(d0));
                asm("add.rn.f32x2 %0, %0, %1;" : "+l"(acc1[i]) : "l"(d1));
            }
        }
#pragma unroll
        for (int i = 0; i < ROWS_B; i++) {
            unsigned x0, x1, x2, x3;
            asm("mov.b64 {%0, %1}, %2;" : "=r"(x0), "=r"(x1) : "l"(acc0[i]));
            asm("mov.b64 {%0, %1}, %2;" : "=r"(x2), "=r"(x3) : "l"(acc1[i]));
            float4 wv = make_float4(__uint_as_float(x0), __uint_as_float(x1),
                                    __uint_as_float(x2), __uint_as_float(x3));
            float4 kv = make_float4(__expf(-10.0f * wv.x), __expf(-10.0f * wv.y),
                                    __expf(-10.0f * wv.z), __expf(-10.0f * wv.w));
            *(float4*)&g_W[(size_t)(i0b + i) * NN + j0] = wv;
            *(float4*)&g_K[(size_t)(i0b + i) * NN + j0] = kv;
        }
    }
    post(1, b, tag);
    if (b >= NB_S) return;          // upper half exits; 64 blocks continue
    wait_flags(1, NB_ALL, tag);     // all g_K / g_W rows visible

    // ---- Sinkhorn setup: stage 16 K rows + 16 K^T rows into smem ----
    int i0 = b * ROWS_S;
    {
        const float4* src = (const float4*)&g_K[(size_t)i0 * NN];
        float4* dst = (float4*)sK;
#pragma unroll
        for (int k = 0; k < 16; k++) dst[t + k * NT] = __ldcg(src + t + k * NT);

#pragma unroll
        for (int r = 0; r < 4; r++) {
            int i = t * 4 + r;
            const float* row = &g_K[(size_t)i * NN + i0];
            float4 x0 = __ldcg((const float4*)(row));
            float4 x1 = __ldcg((const float4*)(row + 4));
            float4 x2 = __ldcg((const float4*)(row + 8));
            float4 x3 = __ldcg((const float4*)(row + 12));
            sKT[ 0 * NN + i] = x0.x; sKT[ 1 * NN + i] = x0.y;
            sKT[ 2 * NN + i] = x0.z; sKT[ 3 * NN + i] = x0.w;
            sKT[ 4 * NN + i] = x1.x; sKT[ 5 * NN + i] = x1.y;
            sKT[ 6 * NN + i] = x1.z; sKT[ 7 * NN + i] = x1.w;
            sKT[ 8 * NN + i] = x2.x; sKT[ 9 * NN + i] = x2.y;
            sKT[10 * NN + i] = x2.z; sKT[11 * NN + i] = x2.w;
            sKT[12 * NN + i] = x3.x; sKT[13 * NN + i] = x3.y;
            sKT[14 * NN + i] = x3.z; sKT[15 * NN + i] = x3.w;
        }
        __syncthreads();

        // first u-step is a plain row-sum (v == 1): u0 = 1/rowsum(sK)
        int w = t >> 5, l = t & 31;
        const float* K0 = sK + (2 * w) * NN;
        const float* K1 = K0 + NN;
        float s0 = 0.f, s1 = 0.f;
#pragma unroll
        for (int k = 0; k < 8; k++) {
            int j = (l + k * 32) * 4;
            float4 a = *(const float4*)&K0[j];
            float4 c = *(const float4*)&K1[j];
            s0 += a.x + a.y + a.z + a.w;
            s1 += c.x + c.y + c.z + c.w;
        }
        s0 = warp_sum(s0);
        s1 = warp_sum(s1);
        if (l == 0) {
            g_u[i0 + 2 * w]     = 1.0f / s0;
            g_u[i0 + 2 * w + 1] = 1.0f / s1;
        }
    }
    int slot = 2;
    post(slot, b, tag);
    wait_flags(slot, NB_S, tag);
    slot++;

    // ---- Sinkhorn iterations ----
    for (int it = 0; it < NITERS; it++) {
        halfstep(sKT, g_u, g_v, i0, sVec, t);     // v = 1/(K^T u)
        post(slot, b, tag);
        wait_flags(slot, NB_S, tag);
        slot++;
        if (it < NITERS - 1) {
            halfstep(sK, g_v, g_u, i0, sVec, t);  // u = 1/(K v)
            post(slot, b, tag);
            wait_flags(slot, NB_S, tag);
            slot++;
        }
    }

    // ---- loss = sum_ij u_i K_ij v_j W_ij ----
    {
        ((float4*)sVec)[t] = __ldcg(((const float4*)g_v) + t);
        __syncthreads();
        int w = t >> 5, l = t & 31;
        float u0 = __ldcg(&g_u[i0 + 2 * w]);
        float u1 = __ldcg(&g_u[i0 + 2 * w + 1]);
        const float* K0 = sK + (2 * w) * NN;
        const float* K1 = K0 + NN;
        const float4* W0 = (const float4*)(g_W + (size_t)(i0 + 2 * w) * NN);
        const float4* W1 = (const float4*)(g_W + (size_t)(i0 + 2 * w + 1) * NN);
        float s0 = 0.f, s1 = 0.f;
#pragma unroll
        for (int k = 0; k < 8; k++) {
            int j4 = l + k * 32;
            int j  = j4 * 4;
            float4 vv = *(const float4*)&sVec[j];
            float4 a  = *(const float4*)&K0[j];
            float4 wa = __ldcg(W0 + j4);
            float4 c  = *(const float4*)&K1[j];
            float4 wc = __ldcg(W1 + j4);
            s0 += a.x * wa.x * vv.x + a.y * wa.y * vv.y
                + a.z * wa.z * vv.z + a.w * wa.w * vv.w;
            s1 += c.x * wc.x * vv.x + c.y * wc.y * vv.y
                + c.z * wc.z * vv.z + c.w * wc.w * vv.w;
        }
        s0 = warp_sum(s0) * u0;
        s1 = warp_sum(s1) * u1;
        if (l == 0) sRed[w] = s0 + s1;
        __syncthreads();
        if (t == 0) {
            float tot = 0.f;
#pragma unroll
            for (int i = 0; i < 8; i++) tot += sRed[i];
            g_partial[b] = tot;
        }
    }
    post(slot, b, tag);
    if (b != 0) return;
    wait_flags(slot, NB_S, tag);

    {
        float v = (t < NB_S) ? __ldcg(&g_partial[t]) : 0.f;
        v = block_sum(v, sRed);
        if (t == 0) out[0] = LSCALE * v;
    }
}

#define SMEM_BYTES ((2 * ROWS_S * NN + NN + ROWS_B * CC + 16) * (int)sizeof(float))

extern "C" void kernel_launch(void* const* d_in, const int* in_sizes, int n_in,
                              void* d_out, int out_size) {
    const float* ys = (const float*)d_in[0];
    const float* yt = (const float*)d_in[1];
    cudaFuncSetAttribute(fused_kernel, cudaFuncAttributeMaxDynamicSharedMemorySize,
                         SMEM_BYTES);
    fused_kernel<<<NB_ALL, NT, SMEM_BYTES>>>(ys, yt, (float*)d_out);
}

// round 6
// speedup vs baseline: 3.0866x; 3.0866x over previous
#include <cuda_runtime.h>
#include <math.h>

#define NN 1024
#define CC 64
#define NITERS 20
#define LSCALE 0.001f
#define MV_BLOCKS 128
#define MV_ROWS 8

// ---------------- device globals (no cudaMalloc allowed) ----------------
__device__ float g_psT[CC * NN];   // transposed softmax of y_s[7]  [C][N]
__device__ float g_ptT[CC * NN];   // transposed softmax of y_t[7]  [C][N]
__device__ float g_W [NN * NN];
__device__ float g_K [NN * NN];
__device__ float g_KT[NN * NN];
__device__ float g_u [NN];
__device__ float g_v [NN];
__device__ float g_partial[MV_BLOCKS];

// ---------------- PDL primitives ----------------
__device__ __forceinline__ void pdl_wait() {
    asm volatile("griddepcontrol.wait;" ::: "memory");
}
__device__ __forceinline__ void pdl_signal() {
    asm volatile("griddepcontrol.launch_dependents;" ::: "memory");
}

// ---------------- reductions ----------------
__device__ __forceinline__ float warp_sum(float v) {
#pragma unroll
    for (int o = 16; o > 0; o >>= 1) v += __shfl_down_sync(0xffffffffu, v, o);
    return v;
}
__device__ __forceinline__ float warp_max(float v) {
#pragma unroll
    for (int o = 16; o > 0; o >>= 1) v = fmaxf(v, __shfl_down_sync(0xffffffffu, v, o));
    return v;
}

// ======================= softmax (64 ch x 2 tensors) =======================
__global__ __launch_bounds__(256) void softmax_kernel(const float* __restrict__ ys,
                                                      const float* __restrict__ yt) {
    __shared__ float sc[9];
    int c = blockIdx.x;
    const float* y = (blockIdx.y == 0) ? ys : yt;
    float* pT      = (blockIdx.y == 0) ? g_psT : g_ptT;
    const float* base = y + 7 * NN * CC;
    int t = threadIdx.x;

    float vals[4];
    float mx = -3.4e38f;
#pragma unroll
    for (int k = 0; k < 4; k++) {
        vals[k] = base[(t + k * 256) * CC + c] * 0.5f;   // y/T, T=2
        mx = fmaxf(mx, vals[k]);
    }
    mx = warp_max(mx);
    if ((t & 31) == 0) sc[t >> 5] = mx;
    __syncthreads();
    if (t == 0) {
        float r = -3.4e38f;
#pragma unroll
        for (int i = 0; i < 8; i++) r = fmaxf(r, sc[i]);
        sc[8] = r;
    }
    __syncthreads();
    mx = sc[8];
    __syncthreads();

    float s = 0.f;
#pragma unroll
    for (int k = 0; k < 4; k++) { vals[k] = expf(vals[k] - mx); s += vals[k]; }
    s = warp_sum(s);
    if ((t & 31) == 0) sc[t >> 5] = s;
    __syncthreads();
    if (t == 0) {
        float r = 0.f;
#pragma unroll
        for (int i = 0; i < 8; i++) r += sc[i];
        sc[8] = r;
    }
    __syncthreads();
    float inv = 1.0f / sc[8];
#pragma unroll
    for (int k = 0; k < 4; k++) pT[c * NN + t + k * 256] = vals[k] * inv;
    __syncthreads();
    pdl_signal();
}

// ============ W/K build (8 full rows per block) + fused u1 = 1/rowsum(K) ============
__global__ __launch_bounds__(256) void wk_kernel() {
    __shared__ float sPS[MV_ROWS * CC];
    __shared__ float red[MV_ROWS][8];
    int b = blockIdx.x, t = threadIdx.x;
    int i0 = b * MV_ROWS;

    pdl_wait();   // needs softmax outputs (immediate predecessor)

    for (int idx = t; idx < MV_ROWS * CC; idx += 256) {
        int i = idx >> 6, c = idx & 63;
        sPS[idx] = g_psT[c * NN + i0 + i];
    }
    __syncthreads();

    const unsigned long long SMASK = 0x8000000080000000ULL;
    const unsigned long long AMASK = 0x7FFFFFFF7FFFFFFFULL;
    unsigned long long acc0[MV_ROWS], acc1[MV_ROWS];
#pragma unroll
    for (int i = 0; i < MV_ROWS; i++) { acc0[i] = 0ULL; acc1[i] = 0ULL; }

    int j0 = t * 4;
    for (int c = 0; c < CC; c++) {
        ulonglong2 bv = *(const ulonglong2*)&g_ptT[c * NN + j0];
        unsigned long long nb0 = bv.x ^ SMASK;
        unsigned long long nb1 = bv.y ^ SMASK;
#pragma unroll
        for (int i = 0; i < MV_ROWS; i++) {
            unsigned ai = __float_as_uint(sPS[i * CC + c]);
            unsigned long long aa, d0, d1;
            asm("mov.b64 %0, {%1, %1};" : "=l"(aa) : "r"(ai));
            asm("add.rn.f32x2 %0, %1, %2;" : "=l"(d0) : "l"(aa), "l"(nb0));
            asm("add.rn.f32x2 %0, %1, %2;" : "=l"(d1) : "l"(aa), "l"(nb1));
            d0 &= AMASK;
            d1 &= AMASK;
            asm("add.rn.f32x2 %0, %0, %1;" : "+l"(acc0[i]) : "l"(d0));
            asm("add.rn.f32x2 %0, %0, %1;" : "+l"(acc1[i]) : "l"(d1));
        }
    }

    float rsum[MV_ROWS];
#pragma unroll
    for (int i = 0; i < MV_ROWS; i++) {
        unsigned x0, x1, x2, x3;
        asm("mov.b64 {%0, %1}, %2;" : "=r"(x0), "=r"(x1) : "l"(acc0[i]));
        asm("mov.b64 {%0, %1}, %2;" : "=r"(x2), "=r"(x3) : "l"(acc1[i]));
        float4 wv = make_float4(__uint_as_float(x0), __uint_as_float(x1),
                                __uint_as_float(x2), __uint_as_float(x3));
        float4 kv = make_float4(__expf(-10.0f * wv.x), __expf(-10.0f * wv.y),
                                __expf(-10.0f * wv.z), __expf(-10.0f * wv.w));
        *(float4*)&g_W[(size_t)(i0 + i) * NN + j0] = wv;
        *(float4*)&g_K[(size_t)(i0 + i) * NN + j0] = kv;
        rsum[i] = kv.x + kv.y + kv.z + kv.w;
    }

    // fused first u-step: u1 = 1 / rowsum(K)  (v == 1)
    int w = t >> 5, l = t & 31;
#pragma unroll
    for (int i = 0; i < MV_ROWS; i++) {
        float s = warp_sum(rsum[i]);
        if (l == 0) red[i][w] = s;
    }
    __syncthreads();
    if (t < MV_ROWS) {
        float s = 0.f;
#pragma unroll
        for (int k = 0; k < 8; k++) s += red[t][k];
        g_u[i0 + t] = 1.0f / s;
    }
    __syncthreads();
    pdl_signal();
}

// ======================= transpose K -> KT (64x64 tiles) =======================
__global__ __launch_bounds__(256) void transpose_kernel() {
    __shared__ float s[64][65];
    int t = threadIdx.x;
    int bx = blockIdx.x, by = blockIdx.y;
    int r = t >> 2, q = t & 3;

    pdl_wait();   // g_K written by immediate predecessor

#pragma unroll
    for (int k = 0; k < 4; k++) {
        int c = q * 16 + k * 4;
        float4 x = *(const float4*)&g_K[(size_t)(by * 64 + r) * NN + bx * 64 + c];
        s[r][c + 0] = x.x; s[r][c + 1] = x.y; s[r][c + 2] = x.z; s[r][c + 3] = x.w;
    }
    __syncthreads();
#pragma unroll
    for (int k = 0; k < 4; k++) {
        int c = q * 16 + k * 4;
        float4 x = make_float4(s[c + 0][r], s[c + 1][r], s[c + 2][r], s[c + 3][r]);
        *(float4*)&g_KT[(size_t)(bx * 64 + r) * NN + by * 64 + c] = x;
    }
    __syncthreads();
    pdl_signal();
}

// ================ Sinkhorn half-step matvec: vout = 1/(M . vin) ================
// 128 blocks x 8 rows. M rows are prefetched into registers BEFORE pdl_wait
// (M is stable: written >=2 nodes back), vin is read only after pdl_wait.
// wait_first=1 for the one node whose M was written by its immediate
// predecessor (v1 after the transpose).
__global__ __launch_bounds__(256) void matvec_kernel(const float* __restrict__ M,
                                                     const float* __restrict__ vin,
                                                     float* __restrict__ vout,
                                                     int wait_first) {
    __shared__ float red[MV_ROWS][8];
    int b = blockIdx.x, t = threadIdx.x;
    const float4* Mr = (const float4*)(M + (size_t)b * MV_ROWS * NN);

    if (wait_first) pdl_wait();
    float4 m[MV_ROWS];
#pragma unroll
    for (int r = 0; r < MV_ROWS; r++) m[r] = __ldcg(Mr + r * 256 + t);
    if (!wait_first) pdl_wait();

    float4 v = __ldcg(((const float4*)vin) + t);
    int w = t >> 5, l = t & 31;
#pragma unroll
    for (int r = 0; r < MV_ROWS; r++) {
        float s = m[r].x * v.x + m[r].y * v.y + m[r].z * v.z + m[r].w * v.w;
        s = warp_sum(s);
        if (l == 0) red[r][w] = s;
    }
    __syncthreads();
    if (t < MV_ROWS) {
        float s = 0.f;
#pragma unroll
        for (int k = 0; k < 8; k++) s += red[t][k];
        vout[b * MV_ROWS + t] = 1.0f / s;
    }
    __syncthreads();
    pdl_signal();
}

// ============ loss partials: sum_ij u_i K_ij v_j W_ij over 8 rows ============
__global__ __launch_bounds__(256) void loss_partial_kernel() {
    __shared__ float sc[9];
    int b = blockIdx.x, t = threadIdx.x;
    int i0 = b * MV_ROWS;
    const float4* Kr = (const float4*)(g_K + (size_t)i0 * NN);
    const float4* Wr = (const float4*)(g_W + (size_t)i0 * NN);

    // prefetch stable K and W rows before the wait
    float4 km[MV_ROWS], wm[MV_ROWS];
#pragma unroll
    for (int r = 0; r < MV_ROWS; r++) {
        km[r] = __ldcg(Kr + r * 256 + t);
        wm[r] = __ldcg(Wr + r * 256 + t);
    }
    pdl_wait();   // v (immediate predecessor) becomes safe

    float4 v = __ldcg(((const float4*)g_v) + t);
    float s = 0.f;
#pragma unroll
    for (int r = 0; r < MV_ROWS; r++) {
        float ur = __ldcg(&g_u[i0 + r]);
        s += ur * (km[r].x * wm[r].x * v.x + km[r].y * wm[r].y * v.y
                 + km[r].z * wm[r].z * v.z + km[r].w * wm[r].w * v.w);
    }
    s = warp_sum(s);
    if ((t & 31) == 0) sc[t >> 5] = s;
    __syncthreads();
    if (t == 0) {
        float r = 0.f;
#pragma unroll
        for (int i = 0; i < 8; i++) r += sc[i];
        g_partial[b] = r;
    }
    __syncthreads();
    pdl_signal();
}

__global__ __launch_bounds__(128) void loss_final_kernel(float* __restrict__ out) {
    __shared__ float sc[4];
    int t = threadIdx.x;
    pdl_wait();
    float s = __ldcg(&g_partial[t]);
    s = warp_sum(s);
    if ((t & 31) == 0) sc[t >> 5] = s;
    __syncthreads();
    if (t == 0) {
        float r = sc[0] + sc[1] + sc[2] + sc[3];
        out[0] = LSCALE * r;
    }
}

// ---------------- host: PDL launches on the legacy stream ----------------
static void launch_pdl(const void* func, dim3 grid, dim3 block, void** args) {
    cudaLaunchConfig_t cfg = {};
    cfg.gridDim = grid;
    cfg.blockDim = block;
    cfg.dynamicSmemBytes = 0;
    cfg.stream = 0;   // legacy default stream (what the harness captures)
    cudaLaunchAttribute attr[1];
    attr[0].id = cudaLaunchAttributeProgrammaticStreamSerialization;
    attr[0].val.programmaticStreamSerializationAllowed = 1;
    cfg.attrs = attr;
    cfg.numAttrs = 1;
    cudaLaunchKernelExC(&cfg, func, args);
}

extern "C" void kernel_launch(void* const* d_in, const int* in_sizes, int n_in,
                              void* d_out, int out_size) {
    const float* ys = (const float*)d_in[0];
    const float* yt = (const float*)d_in[1];
    float* out = (float*)d_out;

    {   // softmax
        void* args[] = {(void*)&ys, (void*)&yt};
        launch_pdl((const void*)softmax_kernel, dim3(64, 2), dim3(256), args);
    }
    {   // W/K build + u1
        void* args[] = {};
        launch_pdl((const void*)wk_kernel, dim3(MV_BLOCKS), dim3(256), args);
    }
    {   // transpose
        void* args[] = {};
        launch_pdl((const void*)transpose_kernel, dim3(16, 16), dim3(256), args);
    }

    // resolve device-global addresses once (host-side, capture-safe: pure lookups)
    static float *pK = nullptr, *pKT = nullptr, *pU = nullptr, *pV = nullptr;
    if (!pK) {
        cudaGetSymbolAddress((void**)&pK,  g_K);
        cudaGetSymbolAddress((void**)&pKT, g_KT);
        cudaGetSymbolAddress((void**)&pU,  g_u);
        cudaGetSymbolAddress((void**)&pV,  g_v);
    }

    for (int it = 0; it < NITERS; it++) {
        {   // v = 1/(KT u); first one must wait before touching KT
            int wf = (it == 0) ? 1 : 0;
            void* args[] = {(void*)&pKT, (void*)&pU, (void*)&pV, (void*)&wf};
            launch_pdl((const void*)matvec_kernel, dim3(MV_BLOCKS), dim3(256), args);
        }
        if (it < NITERS - 1) {   // u = 1/(K v)
            int wf = 0;
            void* args[] = {(void*)&pK, (void*)&pV, (void*)&pU, (void*)&wf};
            launch_pdl((const void*)matvec_kernel, dim3(MV_BLOCKS), dim3(256), args);
        }
    }

    {   // loss partials
        void* args[] = {};
        launch_pdl((const void*)loss_partial_kernel, dim3(MV_BLOCKS), dim3(256), args);
    }
    {   // final reduce
        void* args[] = {(void*)&out};
        launch_pdl((const void*)loss_final_kernel, dim3(1), dim3(128), args);
    }
}